// round 5
// baseline (speedup 1.0000x reference)
#include <cuda_runtime.h>

// ---------------------------------------------------------------------------
// 2-layer LSTM decoder, persistent CTA = 32 batch rows, f32x2 FFMA GEMVs.
// Round-5: proj/sampler split into standalone kernel; ping-pong h buffers
// (2 barriers/step); depth-2 weight prefetch rings.
// ---------------------------------------------------------------------------

#define ULL unsigned long long
#define T_STEPS 20
#define HP 36   // h row stride (floats), 16B-aligned
#define CP 33   // c row stride: conflict-free per-thread access

__device__ __forceinline__ ULL pack2(float x, float y) {
    ULL r; asm("mov.b64 %0, {%1, %2};" : "=l"(r) : "f"(x), "f"(y)); return r;
}
__device__ __forceinline__ float2 unpack2(ULL v) {
    float2 r; asm("mov.b64 {%0, %1}, %2;" : "=f"(r.x), "=f"(r.y) : "l"(v)); return r;
}
__device__ __forceinline__ ULL fma2(ULL a, ULL b, ULL c) {
    ULL d; asm("fma.rn.f32x2 %0, %1, %2, %3;" : "=l"(d) : "l"(a), "l"(b), "l"(c)); return d;
}
__device__ __forceinline__ float sigf(float x)  { return __fdividef(1.f, 1.f + __expf(-x)); }
__device__ __forceinline__ float tanhe(float x) { return __fdividef(2.f, 1.f + __expf(-2.f * x)) - 1.f; }

__device__ float4 g_w1q [64  * 256];           // W1 gate quads
__device__ float4 g_u1q [256 * 256 + 512];     // U1 quads (+pad for ring)
__device__ float4 g_w2q [256 * 256 + 512];     // W2 quads
__device__ float4 g_u2q [256 * 256 + 512];     // U2 quads
__device__ float4 g_xw1q[8192 * 256];          // xw1 quads [row][u], bias folded

__global__ void repack_kernel(const float* __restrict__ W1, const float* __restrict__ U1,
                              const float* __restrict__ W2, const float* __restrict__ U2) {
    int i = blockIdx.x * blockDim.x + threadIdx.x;   // 0..65535
    int k = i >> 8, u = i & 255;
    const float* r;
    if (i < 64 * 256) {
        r = W1 + k * 1024;
        g_w1q[i] = make_float4(r[u], r[256 + u], r[512 + u], r[768 + u]);
    }
    r = U1 + k * 1024; g_u1q[i] = make_float4(r[u], r[256 + u], r[512 + u], r[768 + u]);
    r = W2 + k * 1024; g_w2q[i] = make_float4(r[u], r[256 + u], r[512 + u], r[768 + u]);
    r = U2 + k * 1024; g_u2q[i] = make_float4(r[u], r[256 + u], r[512 + u], r[768 + u]);
}

__global__ void xw1_kernel(const float* __restrict__ z1, const float* __restrict__ z2,
                           const float* __restrict__ b1) {
    __shared__ float zt[8][64];
    const int tid = threadIdx.x;
    const int rb  = blockIdx.x * 8;
    for (int i = tid; i < 512; i += 256) {
        int r = i >> 6, k = i & 63;
        zt[r][k] = (k < 32) ? z1[(rb + r) * 32 + k] : z2[(rb + r) * 32 + (k - 32)];
    }
    __syncthreads();
    const int u = tid;
    float4 acc[8];
    #pragma unroll
    for (int r = 0; r < 8; r++) acc[r] = make_float4(0.f, 0.f, 0.f, 0.f);
    for (int k = 0; k < 64; k++) {
        float4 w = g_w1q[k * 256 + u];
        #pragma unroll
        for (int r = 0; r < 8; r++) {
            float zv = zt[r][k];
            acc[r].x += zv * w.x; acc[r].y += zv * w.y;
            acc[r].z += zv * w.z; acc[r].w += zv * w.w;
        }
    }
    float4 bq = make_float4(b1[u], b1[256 + u], b1[512 + u], b1[768 + u]);
    #pragma unroll
    for (int r = 0; r < 8; r++)
        g_xw1q[(size_t)(rb + r) * 256 + u] =
            make_float4(acc[r].x + bq.x, acc[r].y + bq.y, acc[r].z + bq.z, acc[r].w + bq.w);
}

// SMEM: h1[2][256][HP], h2[2][256][HP], c1/c2 [256][CP]
#define SMEM_FLOATS (4 * 256 * HP + 2 * 256 * CP)
#define SMEM_BYTES  (SMEM_FLOATS * 4)

__global__ void __launch_bounds__(512, 1) lstm_kernel(
    const float* __restrict__ b2, float* __restrict__ out)
{
    extern __shared__ float sm[];
    float* h1b[2] = { sm,                sm + 256 * HP };
    float* h2b[2] = { sm + 2 * 256 * HP, sm + 3 * 256 * HP };
    float* c1s = sm + 4 * 256 * HP;
    float* c2s = c1s + 256 * CP;

    const int tid = threadIdx.x;
    const int u   = tid & 255;
    const int rg  = tid >> 8;
    const int r0  = rg * 16;
    const int rb  = blockIdx.x * 32;

    for (int i = tid; i < SMEM_FLOATS; i += 512) sm[i] = 0.f;
    __syncthreads();

    const ULL b2i = pack2(b2[u], b2[u]);
    const ULL b2f = pack2(b2[256 + u], b2[256 + u]);
    const ULL b2g = pack2(b2[512 + u], b2[512 + u]);
    const ULL b2o = pack2(b2[768 + u], b2[768 + u]);

    const float4* xq = g_xw1q + (size_t)(rb + r0) * 256 + u;

    ULL acc[4][8];
    int pp = 0;  // ping-pong selector: read h[pp], write h[pp^1]

    for (int t = 0; t < T_STEPS; t++) {
        // ================= layer 1: acc = xw1 + h1[pp] @ U1 =================
        #pragma unroll
        for (int p = 0; p < 8; p++) {
            float4 q0 = xq[(2 * p) * 256];
            float4 q1 = xq[(2 * p + 1) * 256];
            acc[0][p] = pack2(q0.x, q1.x);
            acc[1][p] = pack2(q0.y, q1.y);
            acc[2][p] = pack2(q0.z, q1.z);
            acc[3][p] = pack2(q0.w, q1.w);
        }
        {
            float4 w0 = g_u1q[u];
            float4 w1 = g_u1q[256 + u];
            const char* hb = (const char*)(h1b[pp] + r0);
            #pragma unroll 2
            for (int k = 0; k < 256; k++) {
                float4 wn = g_u1q[(k + 2) * 256 + u];       // depth-2 ring
                ULL wi = pack2(w0.x, w0.x), wf = pack2(w0.y, w0.y);
                ULL wg = pack2(w0.z, w0.z), wo = pack2(w0.w, w0.w);
                const ulonglong2* hp = (const ulonglong2*)(hb + (size_t)k * (HP * 4));
                ulonglong2 a0 = hp[0], a1 = hp[1];
                #pragma unroll
                for (int p = 0; p < 4; p++) {
                    ULL hv = (p == 0) ? a0.x : (p == 1) ? a0.y : (p == 2) ? a1.x : a1.y;
                    acc[0][p] = fma2(hv, wi, acc[0][p]);
                    acc[1][p] = fma2(hv, wf, acc[1][p]);
                    acc[2][p] = fma2(hv, wg, acc[2][p]);
                    acc[3][p] = fma2(hv, wo, acc[3][p]);
                }
                ulonglong2 a2 = hp[2], a3 = hp[3];
                #pragma unroll
                for (int p = 4; p < 8; p++) {
                    ULL hv = (p == 4) ? a2.x : (p == 5) ? a2.y : (p == 6) ? a3.x : a3.y;
                    acc[0][p] = fma2(hv, wi, acc[0][p]);
                    acc[1][p] = fma2(hv, wf, acc[1][p]);
                    acc[2][p] = fma2(hv, wg, acc[2][p]);
                    acc[3][p] = fma2(hv, wo, acc[3][p]);
                }
                w0 = w1; w1 = wn;
            }
        }
        // epilogue 1: c1 private, h1 -> other buffer (no pre-barrier needed)
        {
            float* h1n = h1b[pp ^ 1];
            #pragma unroll
            for (int p = 0; p < 8; p++) {
                float2 iv = unpack2(acc[0][p]);
                float2 fv = unpack2(acc[1][p]);
                float2 gv = unpack2(acc[2][p]);
                float2 ov = unpack2(acc[3][p]);
                int rr = r0 + 2 * p;
                float c0 = c1s[u * CP + rr], c1 = c1s[u * CP + rr + 1];
                c0 = sigf(fv.x) * c0 + sigf(iv.x) * tanhe(gv.x);
                c1 = sigf(fv.y) * c1 + sigf(iv.y) * tanhe(gv.y);
                c1s[u * CP + rr]     = c0;
                c1s[u * CP + rr + 1] = c1;
                *(float2*)(h1n + u * HP + rr) =
                    make_float2(sigf(ov.x) * tanhe(c0), sigf(ov.y) * tanhe(c1));
            }
        }
        __syncthreads();                       // (A) h1_new visible; h1[pp]/h2 reads fenced

        // ======== layer 2: acc = b2 + h1[pp^1] @ W2 + h2[pp] @ U2 ========
        #pragma unroll
        for (int p = 0; p < 8; p++) {
            acc[0][p] = b2i; acc[1][p] = b2f; acc[2][p] = b2g; acc[3][p] = b2o;
        }
        {
            float4 w0 = g_w2q[u],      w1 = g_w2q[256 + u];
            float4 v0 = g_u2q[u],      v1 = g_u2q[256 + u];
            const char* hb1 = (const char*)(h1b[pp ^ 1] + r0);
            const char* hb2 = (const char*)(h2b[pp] + r0);
            #pragma unroll 2
            for (int k = 0; k < 256; k++) {
                float4 wn = g_w2q[(k + 2) * 256 + u];
                float4 vn = g_u2q[(k + 2) * 256 + u];
                ULL wi = pack2(w0.x, w0.x), wf = pack2(w0.y, w0.y);
                ULL wg = pack2(w0.z, w0.z), wo = pack2(w0.w, w0.w);
                ULL vi = pack2(v0.x, v0.x), vf = pack2(v0.y, v0.y);
                ULL vg = pack2(v0.z, v0.z), vo = pack2(v0.w, v0.w);
                const ulonglong2* hp1 = (const ulonglong2*)(hb1 + (size_t)k * (HP * 4));
                const ulonglong2* hp2 = (const ulonglong2*)(hb2 + (size_t)k * (HP * 4));
                {
                    ulonglong2 a0 = hp1[0], a1 = hp1[1];
                    ulonglong2 b0 = hp2[0], b1v = hp2[1];
                    #pragma unroll
                    for (int p = 0; p < 4; p++) {
                        ULL h1v = (p == 0) ? a0.x : (p == 1) ? a0.y : (p == 2) ? a1.x : a1.y;
                        ULL h2v = (p == 0) ? b0.x : (p == 1) ? b0.y : (p == 2) ? b1v.x : b1v.y;
                        acc[0][p] = fma2(h1v, wi, acc[0][p]);
                        acc[1][p] = fma2(h1v, wf, acc[1][p]);
                        acc[2][p] = fma2(h1v, wg, acc[2][p]);
                        acc[3][p] = fma2(h1v, wo, acc[3][p]);
                        acc[0][p] = fma2(h2v, vi, acc[0][p]);
                        acc[1][p] = fma2(h2v, vf, acc[1][p]);
                        acc[2][p] = fma2(h2v, vg, acc[2][p]);
                        acc[3][p] = fma2(h2v, vo, acc[3][p]);
                    }
                }
                {
                    ulonglong2 a2 = hp1[2], a3 = hp1[3];
                    ulonglong2 b2v = hp2[2], b3 = hp2[3];
                    #pragma unroll
                    for (int p = 4; p < 8; p++) {
                        ULL h1v = (p == 4) ? a2.x : (p == 5) ? a2.y : (p == 6) ? a3.x : a3.y;
                        ULL h2v = (p == 4) ? b2v.x : (p == 5) ? b2v.y : (p == 6) ? b3.x : b3.y;
                        acc[0][p] = fma2(h1v, wi, acc[0][p]);
                        acc[1][p] = fma2(h1v, wf, acc[1][p]);
                        acc[2][p] = fma2(h1v, wg, acc[2][p]);
                        acc[3][p] = fma2(h1v, wo, acc[3][p]);
                        acc[0][p] = fma2(h2v, vi, acc[0][p]);
                        acc[1][p] = fma2(h2v, vf, acc[1][p]);
                        acc[2][p] = fma2(h2v, vg, acc[2][p]);
                        acc[3][p] = fma2(h2v, vo, acc[3][p]);
                    }
                }
                w0 = w1; w1 = wn; v0 = v1; v1 = vn;
            }
        }
        // epilogue 2: c2 private, h2 -> other buffer, h2 also to gmem
        {
            float* h2n = h2b[pp ^ 1];
            #pragma unroll
            for (int p = 0; p < 8; p++) {
                float2 iv = unpack2(acc[0][p]);
                float2 fv = unpack2(acc[1][p]);
                float2 gv = unpack2(acc[2][p]);
                float2 ov = unpack2(acc[3][p]);
                int rr = r0 + 2 * p;
                float c0 = c2s[u * CP + rr], c1 = c2s[u * CP + rr + 1];
                c0 = sigf(fv.x) * c0 + sigf(iv.x) * tanhe(gv.x);
                c1 = sigf(fv.y) * c1 + sigf(iv.y) * tanhe(gv.y);
                c2s[u * CP + rr]     = c0;
                c2s[u * CP + rr + 1] = c1;
                float2 hn = make_float2(sigf(ov.x) * tanhe(c0), sigf(ov.y) * tanhe(c1));
                *(float2*)(h2n + u * HP + rr) = hn;
                out[((size_t)(rb + rr) * T_STEPS + t) * 256 + u]     = hn.x;
                out[((size_t)(rb + rr + 1) * T_STEPS + t) * 256 + u] = hn.y;
            }
        }
        __syncthreads();                       // (B) h2_new visible; h2[pp]/h1[pp^1] reads fenced
        pp ^= 1;
    }
}

// ---------------------------------------------------------------------------
// Standalone projection + sampler: for each (row,t) in [163840), compute
// mu = h2 @ Wmu + bmu, lv = h2 @ Wlv + blv, sample = eps*exp(0.5*mu)+lv.
// Block = 160 threads (1 col each: 80 mu + 80 lv), 32 rt-rows per block.
// ---------------------------------------------------------------------------
#define PBLK 160
#define PRT  32
#define PHP  36

__global__ void __launch_bounds__(PBLK) proj_kernel(
    const float* __restrict__ Wmu, const float* __restrict__ bmu,
    const float* __restrict__ Wlv, const float* __restrict__ blv,
    const float* __restrict__ eps, float* __restrict__ out)
{
    __shared__ float hs[256 * PHP];      // h2 tile [k][rt], stride 36 (16B aligned)
    __shared__ float lvs[80 * PRT];      // lv exchange for sampler

    const int tid = threadIdx.x;
    const size_t rtb = (size_t)blockIdx.x * PRT;

    // load h2 tile: out[(rtb+r)*256 + k] -> hs[k*PHP + r]
    for (int i = tid; i < PRT * 256; i += PBLK) {
        int r = i >> 8, k = i & 255;
        hs[k * PHP + r] = out[(rtb + r) * 256 + k];
    }
    __syncthreads();

    const bool  ismu = tid < 80;
    const int   f    = ismu ? tid : tid - 80;
    const float* W   = ismu ? Wmu : Wlv;
    const float bias = ismu ? bmu[f] : blv[f];

    ULL acc[16];
    #pragma unroll
    for (int q = 0; q < 16; q++) acc[q] = 0ULL;

    #pragma unroll 2
    for (int k = 0; k < 256; k++) {
        float wv = W[k * 80 + f];
        ULL w2 = pack2(wv, wv);
        const ulonglong2* hp = (const ulonglong2*)(hs + k * PHP);
        #pragma unroll
        for (int c = 0; c < 4; c++) {
            ulonglong2 h01 = hp[2 * c], h23 = hp[2 * c + 1];
            acc[4 * c + 0] = fma2(h01.x, w2, acc[4 * c + 0]);
            acc[4 * c + 1] = fma2(h01.y, w2, acc[4 * c + 1]);
            acc[4 * c + 2] = fma2(h23.x, w2, acc[4 * c + 2]);
            acc[4 * c + 3] = fma2(h23.y, w2, acc[4 * c + 3]);
        }
    }

    float res[PRT];
    #pragma unroll
    for (int q = 0; q < 16; q++) {
        float2 v = unpack2(acc[q]);
        res[2 * q]     = v.x + bias;
        res[2 * q + 1] = v.y + bias;
    }

    if (ismu) {
        #pragma unroll
        for (int r = 0; r < PRT; r++)
            out[41943040u + (rtb + r) * 80 + f] = res[r];          // x_mu
    } else {
        #pragma unroll
        for (int r = 0; r < PRT; r++) {
            out[55050240u + (rtb + r) * 80 + f] = res[r];          // x_logvar
            lvs[f * PRT + r] = res[r];
        }
    }
    __syncthreads();
    if (ismu) {
        #pragma unroll
        for (int r = 0; r < PRT; r++) {
            size_t base = (rtb + r) * 80 + f;
            float lv = lvs[f * PRT + r];
            out[68157440u + base] = eps[base] * __expf(0.5f * res[r]) + lv;  // x_sample
        }
    }
}

extern "C" void kernel_launch(void* const* d_in, const int* in_sizes, int n_in,
                              void* d_out, int out_size) {
    // order: x, z1, z2, eps, W1, U1, b1, W2, U2, b2, Wmu, bmu, Wlv, blv
    const float* z1  = (const float*)d_in[1];
    const float* z2  = (const float*)d_in[2];
    const float* eps = (const float*)d_in[3];
    const float* W1  = (const float*)d_in[4];
    const float* U1  = (const float*)d_in[5];
    const float* b1  = (const float*)d_in[6];
    const float* W2  = (const float*)d_in[7];
    const float* U2  = (const float*)d_in[8];
    const float* b2  = (const float*)d_in[9];
    const float* Wmu = (const float*)d_in[10];
    const float* bmu = (const float*)d_in[11];
    const float* Wlv = (const float*)d_in[12];
    const float* blv = (const float*)d_in[13];
    float* out = (float*)d_out;

    cudaFuncSetAttribute(lstm_kernel, cudaFuncAttributeMaxDynamicSharedMemorySize, SMEM_BYTES);

    repack_kernel<<<256, 256>>>(W1, U1, W2, U2);
    xw1_kernel<<<1024, 256>>>(z1, z2, b1);
    lstm_kernel<<<256, 512, SMEM_BYTES>>>(b2, out);
    proj_kernel<<<163840 / PRT, PBLK>>>(Wmu, bmu, Wlv, blv, eps, out);
}